// round 1
// baseline (speedup 1.0000x reference)
#include <cuda_runtime.h>

// SpecEMA: per-(b,f) EMA over T of |x|^2 summed over C, then y = x * rsqrt(s).
// Linear scan decomposition: chunk partials -> sequential combine -> replay.
#define BB 64
#define CC 2
#define TT 4000
#define FF 96
#define NCHUNK 80
#define LCH (TT / NCHUNK)   // 50

#define ALPHA_F 0.99f
// matches jax: float32(1.0 - 0.99)
#define OMA_F ((float)(1.0 - 0.99))

// scratch (allocation-free rule: __device__ globals)
__device__ float g_part[BB * NCHUNK * FF];   // chunk-local EMA from s=0
__device__ float g_start[BB * NCHUNK * FF];  // true state at chunk start

// ---------------- K1: chunk-local partials ----------------
__global__ void __launch_bounds__(384) k1_partials(const float* __restrict__ x) {
    int gid = blockIdx.x * blockDim.x + threadIdx.x;
    if (gid >= BB * NCHUNK * FF) return;
    int f = gid % FF;
    int j = (gid / FF) % NCHUNK;
    int b = gid / (FF * NCHUNK);

    int t0 = j * LCH;
    // x index: ((b*C + c)*T + t)*F + f
    const float* p0 = x + ((b * CC + 0) * TT + t0) * FF + f;
    const float* p1 = x + ((b * CC + 1) * TT + t0) * FF + f;

    float s = 0.0f;
#pragma unroll 10
    for (int t = 0; t < LCH; t++) {
        float x0 = p0[t * FF];
        float x1 = p1[t * FF];
        float abs2 = fmaf(x0, x0, x1 * x1);
        s = fmaf(abs2, OMA_F, s * ALPHA_F);
    }
    g_part[gid] = s;
}

// ---------------- K2: sequential combine across chunks ----------------
__global__ void __launch_bounds__(256) k2_combine(const float* __restrict__ state) {
    int gid = blockIdx.x * blockDim.x + threadIdx.x;
    if (gid >= BB * FF) return;
    int f = gid % FF;
    int b = gid / FF;

    // alpha^L (float loop; error << tolerance and matches sequential scale closely)
    float aL = 1.0f;
#pragma unroll
    for (int i = 0; i < LCH; i++) aL *= ALPHA_F;

    float s = state[f];  // state is [1,1,F] broadcast over b
#pragma unroll 4
    for (int j = 0; j < NCHUNK; j++) {
        int idx = (b * NCHUNK + j) * FF + f;
        g_start[idx] = s;
        s = fmaf(aL, s, g_part[idx]);
    }
}

// ---------------- K3: replay chunks, write outputs + final state ----------------
__global__ void __launch_bounds__(384) k3_output(const float* __restrict__ x,
                                                 float* __restrict__ out,
                                                 float* __restrict__ fstate,
                                                 int write_state) {
    int gid = blockIdx.x * blockDim.x + threadIdx.x;
    if (gid >= BB * NCHUNK * FF) return;
    int f = gid % FF;
    int j = (gid / FF) % NCHUNK;
    int b = gid / (FF * NCHUNK);

    int t0 = j * LCH;
    int base0 = ((b * CC + 0) * TT + t0) * FF + f;
    int base1 = ((b * CC + 1) * TT + t0) * FF + f;

    float s = g_start[(b * NCHUNK + j) * FF + f];
#pragma unroll 10
    for (int t = 0; t < LCH; t++) {
        int o0 = base0 + t * FF;
        int o1 = base1 + t * FF;
        float x0 = x[o0];
        float x1 = x[o1];
        float abs2 = fmaf(x0, x0, x1 * x1);
        s = fmaf(abs2, OMA_F, s * ALPHA_F);
        float r = rsqrtf(s);
        out[o0] = x0 * r;
        out[o1] = x1 * r;
    }
    if (write_state && j == NCHUNK - 1) fstate[b * FF + f] = s;
}

extern "C" void kernel_launch(void* const* d_in, const int* in_sizes, int n_in,
                              void* d_out, int out_size) {
    const float* feat  = (const float*)d_in[0];  // [B,C,T,F] f32
    const float* state = (const float*)d_in[1];  // [1,1,F]   f32
    float* out = (float*)d_out;

    const int n_out_main = BB * CC * TT * FF;          // 49,152,000
    int write_state = (out_size >= n_out_main + BB * FF) ? 1 : 0;
    float* fstate = out + n_out_main;

    const int n_work = BB * NCHUNK * FF;               // 491,520
    dim3 blk(384);
    dim3 grd((n_work + 383) / 384);

    k1_partials<<<grd, blk>>>(feat);

    dim3 blk2(256);
    dim3 grd2((BB * FF + 255) / 256);
    k2_combine<<<grd2, blk2>>>(state);

    k3_output<<<grd, blk>>>(feat, out, fstate, write_state);
}

// round 2
// speedup vs baseline: 1.3134x; 1.3134x over previous
#include <cuda_runtime.h>

// SpecEMA single-pass: decoupled-lookback scan over time chunks.
// s_t = (1-a)*|x_t|^2 + a*s_{t-1},  y_t = x_t * rsqrt(s_t)
#define BB 64
#define CC 2
#define TT 4000
#define FF 96
#define NCH 125
#define LCH 32          // TT = NCH * LCH exactly

#define ALPHA_F 0.99f
#define OMA_F ((float)(1.0 - 0.99))   // float32(1 - 0.99), matches jax

// ---- scratch (__device__ globals; no allocation allowed) ----
__device__ float g_agg[BB * NCH * FF];   // chunk-local aggregate (from s=0)
__device__ float g_inc[BB * NCH * FF];   // inclusive prefix state at chunk end
__device__ int   g_flag[BB * NCH];       // 0=empty, 1=aggregate, 2=inclusive
__device__ unsigned int g_ctr;           // dynamic block id counter

__device__ __forceinline__ int ld_acquire(const int* p) {
    int v;
    asm volatile("ld.global.acquire.gpu.b32 %0, [%1];" : "=r"(v) : "l"(p));
    return v;
}
__device__ __forceinline__ void st_release(int* p, int v) {
    asm volatile("st.global.release.gpu.b32 [%0], %1;" :: "l"(p), "r"(v));
}

// alpha^LCH in float (compile-time)
__device__ __forceinline__ float alpha_pow_L() {
    float a = 1.0f;
#pragma unroll
    for (int i = 0; i < LCH; i++) a *= ALPHA_F;
    return a;
}

// ---------------- reset: flags + counter (graph replays reuse globals) ----
__global__ void k_reset() {
    int i = blockIdx.x * blockDim.x + threadIdx.x;
    if (i < BB * NCH) g_flag[i] = 0;
    if (i == 0) g_ctr = 0u;
}

// ---------------- single-pass scan kernel ----------------
__global__ void __launch_bounds__(FF) k_scan(const float* __restrict__ x,
                                             const float* __restrict__ state,
                                             float* __restrict__ out,
                                             float* __restrict__ fstate,
                                             int write_state) {
    __shared__ float xs[LCH][CC][FF];
    __shared__ unsigned s_vbid;
    __shared__ int s_stat;

    const int tid = threadIdx.x;           // == lane f
    if (tid == 0) s_vbid = atomicAdd(&g_ctr, 1u);
    __syncthreads();
    const unsigned vbid = s_vbid;
    const int b = (int)(vbid % BB);        // b fastest -> breadth-first chunks
    const int j = (int)(vbid / BB);
    const int f = tid;
    const float aL = alpha_pow_L();

    const float* p0 = x + (((size_t)b * CC + 0) * TT + (size_t)j * LCH) * FF + f;
    const float* p1 = x + (((size_t)b * CC + 1) * TT + (size_t)j * LCH) * FF + f;

    // ---- phase 1: load chunk into smem, compute aggregate from s=0 ----
    float part = 0.0f;
#pragma unroll
    for (int t = 0; t < LCH; t++) {
        float x0 = p0[(size_t)t * FF];
        float x1 = p1[(size_t)t * FF];
        xs[t][0][f] = x0;
        xs[t][1][f] = x1;
        float abs2 = fmaf(x0, x0, x1 * x1);
        part = fmaf(abs2, OMA_F, part * ALPHA_F);
    }

    const int chain = b * NCH + j;
    const int lane_idx = chain * FF + f;
    g_agg[lane_idx] = part;
    __syncthreads();                // all lanes' agg written
    if (tid == 0) {
        __threadfence();
        st_release(&g_flag[chain], 1);
    }

    // ---- phase 2: lookback for exclusive prefix (state at chunk start) ----
    float start;
    if (j == 0) {
        start = state[f];           // state is [1,1,F], broadcast over b
    } else {
        float acc = 0.0f, w = 1.0f;
        int k = j - 1;
        for (;;) {
            if (tid == 0) {
                int st = ld_acquire(&g_flag[b * NCH + k]);
                int tries = 0;
                while (st == 0) {
                    if (++tries > 16) { __nanosleep(64); tries = 0; }
                    st = ld_acquire(&g_flag[b * NCH + k]);
                }
                s_stat = st;
            }
            __syncthreads();
            int stat = s_stat;
            __syncthreads();        // s_stat may be reused next iteration
            if (stat >= 2) {
                acc = fmaf(w, g_inc[(b * NCH + k) * FF + f], acc);
                break;
            }
            acc = fmaf(w, g_agg[(b * NCH + k) * FF + f], acc);
            w *= aL;
            if (k == 0) {           // consumed chunk0 aggregate; add initial state
                acc = fmaf(w, state[f], acc);
                break;
            }
            k--;
        }
        start = acc;
    }

    // ---- publish inclusive ASAP so successors unblock before our stores ----
    float inc = fmaf(aL, start, part);
    g_inc[lane_idx] = inc;
    __syncthreads();
    if (tid == 0) {
        __threadfence();
        st_release(&g_flag[chain], 2);
    }

    // ---- phase 3: replay chunk from smem, write outputs ----
    float s = start;
    float* o0 = out + (((size_t)b * CC + 0) * TT + (size_t)j * LCH) * FF + f;
    float* o1 = out + (((size_t)b * CC + 1) * TT + (size_t)j * LCH) * FF + f;
#pragma unroll
    for (int t = 0; t < LCH; t++) {
        float x0 = xs[t][0][f];
        float x1 = xs[t][1][f];
        float abs2 = fmaf(x0, x0, x1 * x1);
        s = fmaf(abs2, OMA_F, s * ALPHA_F);
        float r = rsqrtf(s);
        o0[(size_t)t * FF] = x0 * r;
        o1[(size_t)t * FF] = x1 * r;
    }
    if (write_state && j == NCH - 1) fstate[b * FF + f] = s;
}

extern "C" void kernel_launch(void* const* d_in, const int* in_sizes, int n_in,
                              void* d_out, int out_size) {
    const float* feat  = (const float*)d_in[0];   // [B,C,T,F] f32
    const float* state = (const float*)d_in[1];   // [1,1,F]   f32
    float* out = (float*)d_out;

    const int n_out_main = BB * CC * TT * FF;     // 49,152,000
    int write_state = (out_size >= n_out_main + BB * FF) ? 1 : 0;
    float* fstate = out + n_out_main;

    k_reset<<<(BB * NCH + 255) / 256, 256>>>();
    k_scan<<<BB * NCH, FF>>>(feat, state, out, fstate, write_state);
}